// round 4
// baseline (speedup 1.0000x reference)
#include <cuda_runtime.h>

#define ROWS 1024
#define COLS 1024
#define NN (ROWS * COLS)

#define RHOGW 9810.0f            // RHO_W * GRAV
#define INV_SEC_PER_A (1.0f / 31556926.0f)
#define FLOW_COEFF 0.0405f

#define TS 48                    // output tile
#define KF 8                     // fused iterations per launch
#define RW 64                    // region width/height (TS + 2*KF)
#define BROWS 34                 // compacted interface rows: 32 + 2 guards
#define EPITCH 17                // edge-column buffer pitch (conflict-free)

// Scratch (device globals: no allocations allowed)
__device__ float4 g_w4[NN];      // incoming weights: {left, right, up, down}
__device__ float  g_runoff[NN];
__device__ float  g_q[2][NN];

// ---------------- fused prep: phi -> gs -> w4 + runoff, one pass ----------------
#define PT 32
#define PH2 36
#define PH1 34

__global__ __launch_bounds__(256) void k_prep(const float* __restrict__ melt,
                                              const float* __restrict__ bed,
                                              const float* __restrict__ wp,
                                              const float* __restrict__ area,
                                              const int*  __restrict__ status) {
    __shared__ float sphi[PH2 * PH2];
    __shared__ float sgs[PH1 * PH1];
    const int ox = blockIdx.x * PT, oy = blockIdx.y * PT;

    for (int idx = threadIdx.x; idx < PH2 * PH2; idx += 256) {
        int iy = idx / PH2, ix = idx % PH2;
        int gy = oy + iy - 2, gx = ox + ix - 2;
        float p = __int_as_float(0x7f800000);     // +INF sentinel: contributes 0 drop
        if (gx >= 0 && gx < COLS && gy >= 0 && gy < ROWS) {
            int g = gy * COLS + gx;
            p = fmaf(RHOGW, bed[g], wp[g]);
        }
        sphi[idx] = p;
    }
    __syncthreads();

    for (int idx = threadIdx.x; idx < PH1 * PH1; idx += 256) {
        int iy = idx / PH1, ix = idx % PH1;
        int gy = oy + iy - 1, gx = ox + ix - 1;
        float gs = 0.0f;
        if (gx >= 0 && gx < COLS && gy >= 0 && gy < ROWS) {
            int g = gy * COLS + gx;
            if (status[g] == 0) {
                int c = (iy + 1) * PH2 + (ix + 1);
                float p = sphi[c];
                float s = 0.0f;
                s += fmaxf(p - sphi[c - 1], 0.0f);
                s += fmaxf(p - sphi[c + 1], 0.0f);
                s += fmaxf(p - sphi[c - PH2], 0.0f);
                s += fmaxf(p - sphi[c + PH2], 0.0f);
                gs = (s > 0.0f) ? (1.0f / s) : 1.0f;
            }
        }
        sgs[idx] = gs;
    }
    __syncthreads();

    for (int idx = threadIdx.x; idx < PT * PT; idx += 256) {
        int iy = idx / PT, ix = idx % PT;
        int gy = oy + iy, gx = ox + ix;
        int g = gy * COLS + gx;
        int cp = (iy + 2) * PH2 + (ix + 2);
        int cg = (iy + 1) * PH1 + (ix + 1);
        float p = sphi[cp];
        float4 w = make_float4(0.0f, 0.0f, 0.0f, 0.0f);
        if (gx > 0)        w.x = fmaxf(sphi[cp - 1]   - p, 0.0f) * sgs[cg - 1];
        if (gx < COLS - 1) w.y = fmaxf(sphi[cp + 1]   - p, 0.0f) * sgs[cg + 1];
        if (gy > 0)        w.z = fmaxf(sphi[cp - PH2] - p, 0.0f) * sgs[cg - PH1];
        if (gy < ROWS - 1) w.w = fmaxf(sphi[cp + PH2] - p, 0.0f) * sgs[cg + PH1];
        g_w4[g] = w;
        g_runoff[g] = melt[g] * area[g] * INV_SEC_PER_A;
    }
}

// ---------------- fused Jacobi: 8 iters, 4x4 patch per thread ----------------
// 256 threads (16x16), each owns a 4x4 patch of a 64x64 region (48x48 tile,
// halo 8). Weights/runoff/q in registers. Vertical interface rows ping-pong in
// a compacted smem buffer (LDS.128/STS.128); horizontal edge columns ping-pong
// in pitch-17 column buffers (stride-1 lanes, conflict-free).
template <bool INIT, bool FINAL>
__global__ __launch_bounds__(256, 2)
void k_fused(int qsel,
             const float* __restrict__ conduit,
             const int*  __restrict__ status,
             float* __restrict__ out) {
    __shared__ __align__(16) float buf[2][BROWS * RW];
    __shared__ float eL[2][RW * EPITCH];   // each thread's c=0 column, [row][tx]
    __shared__ float eR[2][RW * EPITCH];   // each thread's c=3 column

    const int tid = threadIdx.x;
    const int tx = tid & 15, ty = tid >> 4;
    const int px = tx * 4, py = ty * 4;
    const int ox = blockIdx.x * TS - KF;
    const int oy = blockIdx.y * TS - KF;

    const float* __restrict__ qsrc = g_q[qsel];
    float*       __restrict__ qdst = g_q[qsel ^ 1];

    // compacted buffer row indices (regions rows r with r%4 in {0,3} only)
    const int idxT  = 2 * ty;        // region row py-1 (row 0 = guard for ty==0)
    const int idxB  = 2 * ty + 3;    // region row py+4 (row 33 = guard for ty==15)
    const int idxW0 = 2 * ty + 1;    // own row r=0
    const int idxW3 = 2 * ty + 2;    // own row r=3

    float4 w[4][4];
    float  ro[4][4];
    float  q[4][4];
#pragma unroll
    for (int r = 0; r < 4; r++) {
        const int gy = oy + py + r;
        const int gx = ox + px;                  // multiple of 4 -> 16B aligned
        const bool ok = (gy >= 0) & (gy < ROWS) & (gx >= 0) & (gx < COLS);
        const int g = gy * COLS + gx;
        if (ok) {
#pragma unroll
            for (int c = 0; c < 4; c++) w[r][c] = g_w4[g + c];
            float4 rv = *(const float4*)&g_runoff[g];
            ro[r][0] = rv.x; ro[r][1] = rv.y; ro[r][2] = rv.z; ro[r][3] = rv.w;
            float4 qv = INIT ? rv : *(const float4*)&qsrc[g];
            q[r][0] = qv.x; q[r][1] = qv.y; q[r][2] = qv.z; q[r][3] = qv.w;
        } else {
#pragma unroll
            for (int c = 0; c < 4; c++) {
                w[r][c] = make_float4(0.0f, 0.0f, 0.0f, 0.0f);
                ro[r][c] = 0.0f;
                q[r][c] = 0.0f;
            }
        }
    }

    // zero guard rows in both interface buffers
    if (tid < RW) {
        buf[0][tid] = 0.0f; buf[0][(BROWS - 1) * RW + tid] = 0.0f;
        buf[1][tid] = 0.0f; buf[1][(BROWS - 1) * RW + tid] = 0.0f;
    }
    // seed interfaces (iteration-0 values)
    *(float4*)&buf[0][idxW0 * RW + px] = make_float4(q[0][0], q[0][1], q[0][2], q[0][3]);
    *(float4*)&buf[0][idxW3 * RW + px] = make_float4(q[3][0], q[3][1], q[3][2], q[3][3]);
#pragma unroll
    for (int r = 0; r < 4; r++) {
        eL[0][(py + r) * EPITCH + tx] = q[r][0];
        eR[0][(py + r) * EPITCH + tx] = q[r][3];
    }
    __syncthreads();

#pragma unroll
    for (int it = 0; it < KF; it++) {
        const int cur = it & 1, nxt = cur ^ 1;

        float4 t4 = *(const float4*)&buf[cur][idxT * RW + px];
        float4 b4 = *(const float4*)&buf[cur][idxB * RW + px];
        float lf[4], rt[4];
#pragma unroll
        for (int r = 0; r < 4; r++) {
            float lv = 0.0f, rv = 0.0f;
            if (tx > 0)  lv = eR[cur][(py + r) * EPITCH + tx - 1];
            if (tx < 15) rv = eL[cur][(py + r) * EPITCH + tx + 1];
            lf[r] = lv; rt[r] = rv;
        }
        const float tq[4] = {t4.x, t4.y, t4.z, t4.w};
        const float bq[4] = {b4.x, b4.y, b4.z, b4.w};

        float n[4][4];
#pragma unroll
        for (int r = 0; r < 4; r++) {
#pragma unroll
            for (int c = 0; c < 4; c++) {
                const float L = (c == 0) ? lf[r] : q[r][c - 1];
                const float R = (c == 3) ? rt[r] : q[r][c + 1];
                const float U = (r == 0) ? tq[c] : q[r - 1][c];
                const float D = (r == 3) ? bq[c] : q[r + 1][c];
                float acc = ro[r][c];
                acc = fmaf(w[r][c].x, L, acc);
                acc = fmaf(w[r][c].y, R, acc);
                acc = fmaf(w[r][c].z, U, acc);
                acc = fmaf(w[r][c].w, D, acc);
                n[r][c] = acc;
            }
        }
#pragma unroll
        for (int r = 0; r < 4; r++)
#pragma unroll
            for (int c = 0; c < 4; c++) q[r][c] = n[r][c];

        // publish interfaces for next iteration
        *(float4*)&buf[nxt][idxW0 * RW + px] = make_float4(q[0][0], q[0][1], q[0][2], q[0][3]);
        *(float4*)&buf[nxt][idxW3 * RW + px] = make_float4(q[3][0], q[3][1], q[3][2], q[3][3]);
#pragma unroll
        for (int r = 0; r < 4; r++) {
            eL[nxt][(py + r) * EPITCH + tx] = q[r][0];
            eR[nxt][(py + r) * EPITCH + tx] = q[r][3];
        }
        __syncthreads();
    }

    // write central 48x48 tile (whole 4x4 patch is in/out per dimension)
    if (px >= KF && px <= TS + KF - 4 && py >= KF && py <= TS + KF - 4) {
#pragma unroll
        for (int r = 0; r < 4; r++) {
            const int gy = oy + py + r;       // >= 0 since py >= 8
            const int gx = ox + px;           // >= 0 since px >= 8
            if (gy < ROWS && gx < COLS) {
                const int g = gy * COLS + gx;
                if (FINAL) {
                    float4 cd4 = *(const float4*)&conduit[g];
                    int4   st  = *(const int4*)&status[g];
                    float o[4];
                    const float cv[4] = {cd4.x, cd4.y, cd4.z, cd4.w};
                    const int   sv[4] = {st.x, st.y, st.z, st.w};
#pragma unroll
                    for (int c = 0; c < 4; c++) {
                        const float cd = cv[c];
                        const float c125 = cd * sqrtf(sqrtf(cd));   // conduit^1.25
                        const float t = q[r][c] * FLOW_COEFF * c125;
                        o[c] = (sv[c] == 0) ? (t * t) : 0.0f;
                    }
                    *(float4*)&out[g] = make_float4(o[0], o[1], o[2], o[3]);
                } else {
                    *(float4*)&qdst[g] = make_float4(q[r][0], q[r][1], q[r][2], q[r][3]);
                }
            }
        }
    }
}

extern "C" void kernel_launch(void* const* d_in, const int* in_sizes, int n_in,
                              void* d_out, int out_size) {
    const float* melt    = (const float*)d_in[0];
    const float* bed     = (const float*)d_in[1];
    const float* wp      = (const float*)d_in[2];
    const float* area    = (const float*)d_in[3];
    const float* conduit = (const float*)d_in[4];
    const int*   status  = (const int*)d_in[5];
    float* out = (float*)d_out;

    dim3 pgrid(COLS / PT, ROWS / PT);
    k_prep<<<pgrid, 256>>>(melt, bed, wp, area, status);

    dim3 grid((COLS + TS - 1) / TS, (ROWS + TS - 1) / TS);   // 22 x 22 tiles
    // 4 launches x 8 fused iterations = 32 iterations total
    k_fused<true,  false><<<grid, 256>>>(0, conduit, status, out);  // runoff -> g_q[1]
    k_fused<false, false><<<grid, 256>>>(1, conduit, status, out);  // g_q[1] -> g_q[0]
    k_fused<false, false><<<grid, 256>>>(0, conduit, status, out);  // g_q[0] -> g_q[1]
    k_fused<false, true ><<<grid, 256>>>(1, conduit, status, out);  // g_q[1] -> out
}

// round 5
// speedup vs baseline: 1.3324x; 1.3324x over previous
#include <cuda_runtime.h>

#define ROWS 1024
#define COLS 1024
#define NN (ROWS * COLS)

#define RHOGW 9810.0f            // RHO_W * GRAV
#define INV_SEC_PER_A (1.0f / 31556926.0f)
#define FLOW_COEFF 0.0405f

#define TS 32                    // output tile
#define KF 8                     // fused iterations per launch
#define RW (TS + 2*KF)           // 48
#define RN (RW * RW)             // 2304
#define SPAD RW                  // smem guard pad (one row each side)

// Scratch (device globals: no allocations allowed)
__device__ float4 g_w4[NN];      // incoming weights: {left, right, up, down}
__device__ float  g_runoff[NN];
__device__ float  g_q[2][NN];

// ---------------- fused prep: phi -> gs -> w4 + runoff, one pass ----------------
#define PT 32
#define PH2 36
#define PH1 34

__global__ __launch_bounds__(256) void k_prep(const float* __restrict__ melt,
                                              const float* __restrict__ bed,
                                              const float* __restrict__ wp,
                                              const float* __restrict__ area,
                                              const int*  __restrict__ status) {
    __shared__ float sphi[PH2 * PH2];
    __shared__ float sgs[PH1 * PH1];
    const int ox = blockIdx.x * PT, oy = blockIdx.y * PT;

    for (int idx = threadIdx.x; idx < PH2 * PH2; idx += 256) {
        int iy = idx / PH2, ix = idx % PH2;
        int gy = oy + iy - 2, gx = ox + ix - 2;
        float p = __int_as_float(0x7f800000);     // +INF sentinel: contributes 0 drop
        if (gx >= 0 && gx < COLS && gy >= 0 && gy < ROWS) {
            int g = gy * COLS + gx;
            p = fmaf(RHOGW, bed[g], wp[g]);
        }
        sphi[idx] = p;
    }
    __syncthreads();

    for (int idx = threadIdx.x; idx < PH1 * PH1; idx += 256) {
        int iy = idx / PH1, ix = idx % PH1;
        int gy = oy + iy - 1, gx = ox + ix - 1;
        float gs = 0.0f;
        if (gx >= 0 && gx < COLS && gy >= 0 && gy < ROWS) {
            int g = gy * COLS + gx;
            if (status[g] == 0) {
                int c = (iy + 1) * PH2 + (ix + 1);
                float p = sphi[c];
                float s = 0.0f;
                s += fmaxf(p - sphi[c - 1], 0.0f);
                s += fmaxf(p - sphi[c + 1], 0.0f);
                s += fmaxf(p - sphi[c - PH2], 0.0f);
                s += fmaxf(p - sphi[c + PH2], 0.0f);
                gs = (s > 0.0f) ? (1.0f / s) : 1.0f;
            }
        }
        sgs[idx] = gs;
    }
    __syncthreads();

    for (int idx = threadIdx.x; idx < PT * PT; idx += 256) {
        int iy = idx / PT, ix = idx % PT;
        int gy = oy + iy, gx = ox + ix;
        int g = gy * COLS + gx;
        int cp = (iy + 2) * PH2 + (ix + 2);
        int cg = (iy + 1) * PH1 + (ix + 1);
        float p = sphi[cp];
        float4 w = make_float4(0.0f, 0.0f, 0.0f, 0.0f);
        if (gx > 0)        w.x = fmaxf(sphi[cp - 1]   - p, 0.0f) * sgs[cg - 1];
        if (gx < COLS - 1) w.y = fmaxf(sphi[cp + 1]   - p, 0.0f) * sgs[cg + 1];
        if (gy > 0)        w.z = fmaxf(sphi[cp - PH2] - p, 0.0f) * sgs[cg - PH1];
        if (gy < ROWS - 1) w.w = fmaxf(sphi[cp + PH2] - p, 0.0f) * sgs[cg + PH1];
        g_w4[g] = w;
        g_runoff[g] = melt[g] * area[g] * INV_SEC_PER_A;
    }
}

// ---------------- fused Jacobi: 8 iters, 3x3 patch in registers ----------------
// 256 threads (16x16), each owns a 3x3 patch of a 48x48 region (32x32 tile,
// halo 8). Weights in registers, runoff in smem, ring exchange via smem.
// Active-region shrinking: patch computes at iter `it` only if pm >= it-1.
template <bool INIT, bool FINAL>
__global__ __launch_bounds__(256, 4)
void k_fused(int qsel,
             const float* __restrict__ conduit,
             const int*  __restrict__ status,
             float* __restrict__ out) {
    __shared__ float sq[2][RN + 2 * SPAD];
    __shared__ float sro[RN];

    const int tid = threadIdx.x;
    const int tx = tid & 15, ty = tid >> 4;
    const int px = tx * 3, py = ty * 3;
    const int ox = blockIdx.x * TS - KF;
    const int oy = blockIdx.y * TS - KF;

    const float* __restrict__ qsrc = g_q[qsel];
    float*       __restrict__ qdst = g_q[qsel ^ 1];

    // zero guard pads (one row above/below region, never written afterwards)
    if (tid < SPAD) {
        sq[0][tid] = 0.0f;
        sq[1][tid] = 0.0f;
        sq[0][SPAD + RN + tid] = 0.0f;
        sq[1][SPAD + RN + tid] = 0.0f;
    }

    const int rbase = py * RW + px;        // index into sro
    const int base  = SPAD + rbase;        // index into sq
    // patch corner margin to region edge
    const int pm = min(min(px, py), min(45 - px, 45 - py));

    float4 w[3][3];
    float  q[3][3];
#pragma unroll
    for (int r = 0; r < 3; r++) {
#pragma unroll
        for (int c = 0; c < 3; c++) {
            const int gy = oy + py + r, gx = ox + px + c;
            const bool ok = (gx >= 0) & (gx < COLS) & (gy >= 0) & (gy < ROWS);
            const int g = gy * COLS + gx;
            float4 wv = make_float4(0.0f, 0.0f, 0.0f, 0.0f);
            float rv = 0.0f, qv = 0.0f;
            if (ok) {
                wv = g_w4[g];
                rv = g_runoff[g];
                qv = INIT ? rv : qsrc[g];
            }
            w[r][c] = wv; q[r][c] = qv;
            sro[rbase + r * RW + c] = rv;
            if (!(r == 1 && c == 1)) sq[0][base + r * RW + c] = qv;  // seed borders
        }
    }
    __syncthreads();

#pragma unroll
    for (int it = 0; it < KF; it++) {
        const int cur = it & 1;
        const float* __restrict__ qs = sq[cur];
        float*       __restrict__ qd = sq[cur ^ 1];

        if (pm >= it - 1) {
            // 12-ring from neighboring threads (previous iteration values)
            float t0 = qs[base - RW],     t1 = qs[base - RW + 1],     t2 = qs[base - RW + 2];
            float b0 = qs[base + 3 * RW], b1 = qs[base + 3 * RW + 1], b2 = qs[base + 3 * RW + 2];
            float l0 = qs[base - 1],      l1 = qs[base + RW - 1],     l2 = qs[base + 2 * RW - 1];
            float r0 = qs[base + 3],      r1 = qs[base + RW + 3],     r2 = qs[base + 2 * RW + 3];

            float n[3][3];
#pragma unroll
            for (int r = 0; r < 3; r++) {
#pragma unroll
                for (int c = 0; c < 3; c++) {
                    const float lf = (c == 0) ? ((r == 0) ? l0 : (r == 1) ? l1 : l2) : q[r][c - 1];
                    const float rt = (c == 2) ? ((r == 0) ? r0 : (r == 1) ? r1 : r2) : q[r][c + 1];
                    const float up = (r == 0) ? ((c == 0) ? t0 : (c == 1) ? t1 : t2) : q[r - 1][c];
                    const float dn = (r == 2) ? ((c == 0) ? b0 : (c == 1) ? b1 : b2) : q[r + 1][c];
                    float acc = sro[rbase + r * RW + c];
                    acc = fmaf(w[r][c].x, lf, acc);
                    acc = fmaf(w[r][c].y, rt, acc);
                    acc = fmaf(w[r][c].z, up, acc);
                    acc = fmaf(w[r][c].w, dn, acc);
                    n[r][c] = acc;
                }
            }
#pragma unroll
            for (int r = 0; r < 3; r++)
#pragma unroll
                for (int c = 0; c < 3; c++) q[r][c] = n[r][c];

            if (it != KF - 1) {
                // publish only the 8 border cells of the patch
                qd[base]              = q[0][0];
                qd[base + 1]          = q[0][1];
                qd[base + 2]          = q[0][2];
                qd[base + RW]         = q[1][0];
                qd[base + RW + 2]     = q[1][2];
                qd[base + 2 * RW]     = q[2][0];
                qd[base + 2 * RW + 1] = q[2][1];
                qd[base + 2 * RW + 2] = q[2][2];
            }
        }
        if (it != KF - 1) __syncthreads();
    }

    // write central 32x32 from registers
#pragma unroll
    for (int r = 0; r < 3; r++) {
#pragma unroll
        for (int c = 0; c < 3; c++) {
            const int ly = py + r, lx = px + c;
            if (lx >= KF && lx < KF + TS && ly >= KF && ly < KF + TS) {
                const int g = (oy + ly) * COLS + (ox + lx);
                if (FINAL) {
                    const float cd = conduit[g];
                    const float c125 = cd * sqrtf(sqrtf(cd));   // conduit^1.25
                    const float t = q[r][c] * FLOW_COEFF * c125;
                    out[g] = (status[g] == 0) ? (t * t) : 0.0f;
                } else {
                    qdst[g] = q[r][c];
                }
            }
        }
    }
}

extern "C" void kernel_launch(void* const* d_in, const int* in_sizes, int n_in,
                              void* d_out, int out_size) {
    const float* melt    = (const float*)d_in[0];
    const float* bed     = (const float*)d_in[1];
    const float* wp      = (const float*)d_in[2];
    const float* area    = (const float*)d_in[3];
    const float* conduit = (const float*)d_in[4];
    const int*   status  = (const int*)d_in[5];
    float* out = (float*)d_out;

    dim3 pgrid(COLS / PT, ROWS / PT);
    k_prep<<<pgrid, 256>>>(melt, bed, wp, area, status);

    dim3 grid(COLS / TS, ROWS / TS);   // 32 x 32 tiles
    // 4 launches x 8 fused iterations = 32 iterations total
    k_fused<true,  false><<<grid, 256>>>(0, conduit, status, out);  // runoff -> g_q[1]
    k_fused<false, false><<<grid, 256>>>(1, conduit, status, out);  // g_q[1] -> g_q[0]
    k_fused<false, false><<<grid, 256>>>(0, conduit, status, out);  // g_q[0] -> g_q[1]
    k_fused<false, true ><<<grid, 256>>>(1, conduit, status, out);  // g_q[1] -> out
}